// round 8
// baseline (speedup 1.0000x reference)
#include <cuda_runtime.h>
#include <cuda_bf16.h>
#include <math.h>
#include <stdint.h>

#define NF 96
#define GD 12
#define K2T 9
#define BN 4
#define HH 128
#define WW 128
#define HWSZ (HH*WW)
typedef unsigned short ushort;

__device__ float g_t1[BN*NF*HWSZ];
__device__ float g_t2[BN*NF*HWSZ];
__device__ float g_e1[BN*NF*64*64];
__device__ float g_d1[BN*NF*64*64];
__device__ float g_off[BN*2*GD*K2T*HWSZ];
// bf16 split planes
__device__ ushort g_xh[BN*192*HWSZ];
__device__ ushort g_xl[BN*192*HWSZ];
__device__ uint32_t g_sh[BN*432*HWSZ];   // S hi, pair-packed [n][432][HW]
__device__ uint32_t g_sl[BN*432*HWSZ];
__device__ uint32_t g_wh[262656];
__device__ uint32_t g_wl[262656];

__device__ __forceinline__ void split2(float v0, float v1, uint32_t& hi, uint32_t& lo){
    __nv_bfloat16 h0=__float2bfloat16(v0), h1=__float2bfloat16(v1);
    __nv_bfloat16 l0=__float2bfloat16(v0-__bfloat162float(h0));
    __nv_bfloat16 l1=__float2bfloat16(v1-__bfloat162float(h1));
    hi=((uint32_t)__bfloat16_as_ushort(h1)<<16)|__bfloat16_as_ushort(h0);
    lo=((uint32_t)__bfloat16_as_ushort(l1)<<16)|__bfloat16_as_ushort(l0);
}

// ---------------- fp32 pipelined 3x3 s1 conv (oc1, oc3) ----------------------
__global__ __launch_bounds__(256) void conv3x3_s1v2(
    const float* __restrict__ inA, int cinA,
    const float* __restrict__ inB, int cinB,
    const float* __restrict__ w, const float* __restrict__ bias,
    float* __restrict__ out, int cout, int flags)
{
    const int tid = threadIdx.x;
    const int tx = tid & 15, ty = tid >> 4;
    const int x0 = (blockIdx.x & 1) * 64, y0 = (blockIdx.x >> 1) * 16;
    const int ocb = blockIdx.y * 8, n = blockIdx.z;
    const int cin = cinA + cinB, nch = cin >> 2;
    __shared__ float sIn[2][4][18][68];
    __shared__ float sW[2][8*4*9];
    float rI[19]; float rw0, rw1;

#define S1_LOAD(IC0) { const int ic0_=(IC0); \
    _Pragma("unroll") for (int k=0;k<19;k++){ int idx=tid+256*k; \
      if (k<18||tid<144){ int ic=idx/1188; int rem=idx-ic*1188; int rr=rem/66; int cc=rem-rr*66; \
        int gy=y0-1+rr, gx=x0-1+cc; bool inb=((unsigned)gy<(unsigned)HH)&&((unsigned)gx<(unsigned)WW); \
        int icg=ic0_+ic; const float* p=(icg<cinA)?(inA+((size_t)(n*cinA+icg)*HH+gy)*WW+gx):(inB+((size_t)(n*cinB+(icg-cinA))*HH+gy)*WW+gx); \
        rI[k]=inb?__ldg(p):0.f; } } \
    { int o=tid/36, ic=(tid/9)%4, t=tid%9; rw0=w[((size_t)(ocb+o)*cin+ic0_+ic)*9+t]; \
      if (tid<32){ int idx=tid+256; int o2=idx/36, ic2=(idx/9)%4, t2=idx%9; rw1=w[((size_t)(ocb+o2)*cin+ic0_+ic2)*9+t2]; } } }
#define S1_STORE(B) { float* sb=&sIn[B][0][0][0]; \
    _Pragma("unroll") for (int k=0;k<19;k++){ int idx=tid+256*k; \
      if (k<18||tid<144){ int ic=idx/1188; int rem=idx-ic*1188; int rr=rem/66; int cc=rem-rr*66; \
        sb[(ic*18+rr)*68+cc]=rI[k]; } } \
    sW[B][tid]=rw0; if (tid<32) sW[B][tid+256]=rw1; }

    float acc[8][4];
#pragma unroll
    for (int o=0;o<8;o++)
#pragma unroll
      for (int j=0;j<4;j++) acc[o][j]=0.f;
    S1_LOAD(0); S1_STORE(0); __syncthreads();
    for (int c=0;c<nch;c++){
        const int b=c&1;
        if (c+1<nch) S1_LOAD((c+1)*4);
#pragma unroll
        for (int ic=0;ic<4;ic++){
#pragma unroll
            for (int dy=0;dy<3;dy++){
                const float* rp=&sIn[b][ic][ty+dy][4*tx];
                float4 va=*(const float4*)rp; float2 vb=*(const float2*)(rp+4);
                float v[6]={va.x,va.y,va.z,va.w,vb.x,vb.y};
                const float* wrow=&sW[b][ic*9+dy*3];
#pragma unroll
                for (int dx=0;dx<3;dx++){
                    float wv[8];
#pragma unroll
                    for (int o=0;o<8;o++) wv[o]=wrow[o*36+dx];
#pragma unroll
                    for (int j=0;j<4;j++){ float xv=v[j+dx];
#pragma unroll
                        for (int o=0;o<8;o++) acc[o][j]=fmaf(wv[o],xv,acc[o][j]); }
                }
            }
        }
        if (c+1<nch){ S1_STORE((c+1)&1); __syncthreads(); }
    }
    const int y=y0+ty, xb=x0+4*tx;
#pragma unroll
    for (int o=0;o<8;o++){
        float bv=bias[ocb+o];
        float v0=acc[o][0]+bv,v1=acc[o][1]+bv,v2=acc[o][2]+bv,v3=acc[o][3]+bv;
        if (flags&1){ v0=(v0>=0.f)?v0:0.1f*v0; v1=(v1>=0.f)?v1:0.1f*v1; v2=(v2>=0.f)?v2:0.1f*v2; v3=(v3>=0.f)?v3:0.1f*v3; }
        float* op=out+((size_t)(n*cout+ocb+o)*HH+y)*WW+xb;
        if (flags&2){ float4 p=*(float4*)op; p.x+=v0;p.y+=v1;p.z+=v2;p.w+=v3; *(float4*)op=p; }
        else *(float4*)op=make_float4(v0,v1,v2,v3);
    }
#undef S1_LOAD
#undef S1_STORE
}

// ---------------- fp32 pipelined 3x3 s2 conv (e1, e2) ------------------------
__global__ __launch_bounds__(256) void conv3x3_s2v2(
    const float* __restrict__ in, int Hin,
    const float* __restrict__ w, const float* __restrict__ bias,
    float* __restrict__ out, float* __restrict__ out_q, int flags)
{
    const int tid=threadIdx.x, tx=tid&15, ty=tid>>4;
    const int Hout=Hin>>1, tilesX=Hout>>4;
    const int x0=(blockIdx.x%tilesX)*16, y0=(blockIdx.x/tilesX)*16;
    const int ocb=blockIdx.y*8, n=blockIdx.z;
    __shared__ float sIn[2][2][33][34];
    __shared__ float sW[2][8*2*9];
    float rI[9]; float rw0;
#define S2_LOAD(IC0) { const int ic0_=(IC0); \
    _Pragma("unroll") for (int k=0;k<9;k++){ int idx=tid+256*k; \
      if (k<8||tid<130){ int ic=idx/1089; int rem=idx-ic*1089; int rr=rem/33; int cc=rem-rr*33; \
        int gy=2*y0+rr, gx=2*x0+cc; bool inb=(gy<Hin)&&(gx<Hin); \
        rI[k]=inb?__ldg(in+((size_t)(n*NF+ic0_+ic)*Hin+gy)*Hin+gx):0.f; } } \
    if (tid<144){ int o=tid/18, ic=(tid/9)%2, t=tid%9; rw0=w[((size_t)(ocb+o)*NF+ic0_+ic)*9+t]; } }
#define S2_STORE(B) { float* sb=&sIn[B][0][0][0]; \
    _Pragma("unroll") for (int k=0;k<9;k++){ int idx=tid+256*k; \
      if (k<8||tid<130){ int ic=idx/1089; int rem=idx-ic*1089; int rr=rem/33; int cc=rem-rr*33; \
        sb[(ic*33+rr)*34+cc]=rI[k]; } } \
    if (tid<144) sW[B][tid]=rw0; }
    float acc[8];
#pragma unroll
    for (int o=0;o<8;o++) acc[o]=0.f;
    S2_LOAD(0); S2_STORE(0); __syncthreads();
    const int nch=NF/2;
    for (int c=0;c<nch;c++){
        const int b=c&1;
        if (c+1<nch) S2_LOAD((c+1)*2);
#pragma unroll
        for (int ic=0;ic<2;ic++)
#pragma unroll
            for (int dy=0;dy<3;dy++)
#pragma unroll
                for (int dx=0;dx<3;dx++){
                    float xv=sIn[b][ic][2*ty+dy][2*tx+dx];
                    const float* wp=&sW[b][ic*9+dy*3+dx];
#pragma unroll
                    for (int o=0;o<8;o++) acc[o]=fmaf(wp[o*18],xv,acc[o]);
                }
        if (c+1<nch){ S2_STORE((c+1)&1); __syncthreads(); }
    }
#pragma unroll
    for (int o=0;o<8;o++){
        float v=acc[o]+bias[ocb+o];
        if (flags&1) v=(v>=0.f)?v:0.1f*v;
        size_t oi=((size_t)(n*NF+ocb+o)*Hout+(y0+ty))*Hout+(x0+tx);
        out[oi]=v;
        if (out_q) out_q[oi]=rintf(v);
    }
#undef S2_LOAD
#undef S2_STORE
}

// ---------------- fp32 transpose conv (d1, d2) --------------------------------
__global__ __launch_bounds__(256) void deconv3x3_x2(
    const float* __restrict__ in, int Hin,
    const float* __restrict__ w, const float* __restrict__ bias,
    float* __restrict__ out, int flags)
{
    const int tid=threadIdx.x, tx=tid&15, ty=tid>>4;
    const int Hout=Hin*2, tilesX=Hout>>5;
    const int tX=blockIdx.x%tilesX, tY=blockIdx.x/tilesX;
    const int xin0=tX*16, yin0=tY*16, x0o=tX*32, y0o=tY*32;
    const int ocb=blockIdx.y*8, n=blockIdx.z;
    __shared__ float sIn[4][17][18];
    __shared__ float sW[8][4][9];
    float aEE[8],aEO[8],aOE[8],aOO[8];
#pragma unroll
    for (int o=0;o<8;o++){aEE[o]=0.f;aEO[o]=0.f;aOE[o]=0.f;aOO[o]=0.f;}
    for (int ic0=0;ic0<NF;ic0+=4){
        __syncthreads();
        for (int idx=tid;idx<4*17*17;idx+=256){
            int ic=idx/(17*17), r=(idx/17)%17, c=idx%17;
            int gy=yin0-1+r, gx=xin0-1+c;
            float v=0.f;
            if ((unsigned)gy<(unsigned)Hin&&(unsigned)gx<(unsigned)Hin)
                v=in[((size_t)(n*NF+ic0+ic)*Hin+gy)*Hin+gx];
            sIn[ic][r][c]=v;
        }
        for (int idx=tid;idx<8*4*9;idx+=256){
            int o=idx/36, ic=(idx/9)%4, t=idx%9;
            sW[o][ic][t]=w[((size_t)(ocb+o)*NF+ic0+ic)*9+t];
        }
        __syncthreads();
#pragma unroll
        for (int ic=0;ic<4;ic++){
            float v00=sIn[ic][ty][tx], v01=sIn[ic][ty][tx+1];
            float v10=sIn[ic][ty+1][tx], v11=sIn[ic][ty+1][tx+1];
#pragma unroll
            for (int o=0;o<8;o++){
                const float* wp=&sW[o][ic][0];
                aEE[o]=fmaf(wp[0],v00,aEE[o]); aEE[o]=fmaf(wp[2],v01,aEE[o]);
                aEE[o]=fmaf(wp[6],v10,aEE[o]); aEE[o]=fmaf(wp[8],v11,aEE[o]);
                aEO[o]=fmaf(wp[1],v01,aEO[o]); aEO[o]=fmaf(wp[7],v11,aEO[o]);
                aOE[o]=fmaf(wp[3],v10,aOE[o]); aOE[o]=fmaf(wp[5],v11,aOE[o]);
                aOO[o]=fmaf(wp[4],v11,aOO[o]);
            }
        }
    }
    const int ye=y0o+2*ty, xe=x0o+2*tx;
#pragma unroll
    for (int o=0;o<8;o++){
        float bv=bias[ocb+o];
        float vEE=aEE[o]+bv,vEO=aEO[o]+bv,vOE=aOE[o]+bv,vOO=aOO[o]+bv;
        if (flags&1){ vEE=(vEE>=0.f)?vEE:0.1f*vEE; vEO=(vEO>=0.f)?vEO:0.1f*vEO;
                      vOE=(vOE>=0.f)?vOE:0.1f*vOE; vOO=(vOO>=0.f)?vOO:0.1f*vOO; }
        size_t base=((size_t)(n*NF+ocb+o)*Hout+ye)*Hout+xe;
        out[base]=vEE; out[base+1]=vEO; out[base+Hout]=vOE; out[base+Hout+1]=vOO;
    }
}

// ---------------- DCN sampling -> pair-packed bf16 hi/lo planes ---------------
__global__ __launch_bounds__(256) void dcn_sample(
    const float* __restrict__ ref, const float* __restrict__ off,
    ushort* __restrict__ SH, ushort* __restrict__ SL)
{
    int idx=blockIdx.x*256+threadIdx.x;
    if (idx>=BN*GD*K2T*HWSZ) return;
    int p=idx&(HWSZ-1); int t=idx>>14;
    int k=t%9; t/=9; int g=t%GD, n=t/GD;
    int y=p>>7, x=p&127;
    int offc=(g*9+k)*2;
    float dy=off[((size_t)(n*2*GD*K2T+offc))*HWSZ+p];
    float dx=off[((size_t)(n*2*GD*K2T+offc+1))*HWSZ+p];
    float py=(float)y+(float)(k/3-1)+dy;
    float px=(float)x+(float)(k%3-1)+dx;
    float fy=floorf(py), fx=floorf(px);
    float wy=py-fy, wx=px-fx;
    int iy=(int)fy, ix=(int)fx;
    float wgt[4]; int ofs[4];
#pragma unroll
    for (int r=0;r<2;r++)
#pragma unroll
        for (int c=0;c<2;c++){
            int yy=iy+r, xx=ix+c;
            bool val=((unsigned)yy<(unsigned)HH)&&((unsigned)xx<(unsigned)WW);
            float wv=(r?wy:1.f-wy)*(c?wx:1.f-wx);
            wgt[r*2+c]=val?wv:0.f; ofs[r*2+c]=val?(yy*WW+xx):0;
        }
    const float* base=ref+(size_t)(n*NF+g*8)*HWSZ;
#pragma unroll
    for (int c=0;c<8;c++){
        const float* bp=base+(size_t)c*HWSZ;
        float s=wgt[0]*bp[ofs[0]]+wgt[1]*bp[ofs[1]]+wgt[2]*bp[ofs[2]]+wgt[3]*bp[ofs[3]];
        __nv_bfloat16 hb=__float2bfloat16(s);
        __nv_bfloat16 lb=__float2bfloat16(s-__bfloat162float(hb));
        int ch=((g*8+c)*9+k);
        size_t a=(((size_t)(n*432+(ch>>1)))*HWSZ+p)*2+(ch&1);
        SH[a]=__bfloat16_as_ushort(hb);
        SL[a]=__bfloat16_as_ushort(lb);
    }
}

// ---------------- split fp32 tensor into bf16 hi/lo planes --------------------
__global__ __launch_bounds__(256) void split_tensor(
    const float* __restrict__ in, ushort* __restrict__ hi, ushort* __restrict__ lo,
    int chPerN, int chOff, int totCh)
{
    int p=blockIdx.x*256+threadIdx.x;                 // pair index
    int per=chPerN*HWSZ;
    if (p>=BN*per/2) return;
    int e=p*2;
    int n=e/per, r=e-n*per;
    float2 v=*(const float2*)(in+(size_t)n*per+r);
    uint32_t h,l; split2(v.x,v.y,h,l);
    size_t ob=(((size_t)(n*totCh+chOff))*HWSZ+r)>>1;
    ((uint32_t*)hi)[ob]=h;
    ((uint32_t*)lo)[ob]=l;
}

// ---------------- pre-split weights into [chunk][oc][kpair] -------------------
__global__ __launch_bounds__(256) void w_prep(
    const float* __restrict__ w, int K, int cout, int coutPad,
    uint32_t* __restrict__ WH, uint32_t* __restrict__ WL)
{
    int chunk=blockIdx.x;
    for (int idx=threadIdx.x; idx<coutPad*16; idx+=256){
        int oc=idx>>4, kp=idx&15;
        float v0=0.f, v1=0.f;
        if (oc<cout){ int k0=chunk*32+kp*2; v0=w[(size_t)oc*K+k0]; v1=w[(size_t)oc*K+k0+1]; }
        uint32_t h,l; split2(v0,v1,h,l);
        WH[(size_t)chunk*coutPad*16+idx]=h;
        WL[(size_t)chunk*coutPad*16+idx]=l;
    }
}

// ================= mma.sync bf16 split-3 GEMM (pre-split inputs) =============
#define MMA4(d,a0,a1,a2,a3,b0,b1) \
    asm volatile("mma.sync.aligned.m16n8k16.row.col.f32.bf16.bf16.f32 " \
        "{%0,%1,%2,%3},{%4,%5,%6,%7},{%8,%9},{%0,%1,%2,%3};" \
        : "+f"(d[0]),"+f"(d[1]),"+f"(d[2]),"+f"(d[3]) \
        : "r"(a0),"r"(a1),"r"(a2),"r"(a3),"r"(b0),"r"(b1))

template<int NF8, int MODE>
__global__ __launch_bounds__(256) void gemm_tc(
    const ushort* __restrict__ XH, const ushort* __restrict__ XL, int cin,
    const uint32_t* __restrict__ WH, const uint32_t* __restrict__ WL, int coutPad,
    const float* __restrict__ bias, float* __restrict__ out, int cout, int flags)
{
    extern __shared__ uint32_t sm[];
    const int Ncta = NF8*16;
    const int AW = 128*18, BW = Ncta*18, PB = 2*AW + 2*BW;
    const int tid=threadIdx.x, lane=tid&31, wid=tid>>5;
    const int g=lane>>2, tig=lane&3;
    const int y=blockIdx.x, n=blockIdx.z;
    const int ocb = blockIdx.y * Ncta;
    const int K = MODE ? cin : cin*9;
    const int nch = K/32;
    const int mIdx = (wid&3)*32, nIdx = (wid>>2)*NF8*8;
    const int apx = tid & 127, ah_ = tid >> 7;

    uint32_t pah[8], pal[8], pbh[NF8], pbl[NF8];

#define G_LOAD(C) { const int c_=(C); \
    if (MODE){ \
        const uint32_t* PH=(const uint32_t*)XH; const uint32_t* PL=(const uint32_t*)XL; \
        size_t abase=((size_t)n*(cin>>1))*HWSZ + y*WW + apx; \
        _Pragma("unroll") for (int i=0;i<8;i++){ \
            size_t a_=abase + (size_t)((c_*32+(ah_*8+i)*2)>>1)*HWSZ; \
            pah[i]=__ldg(PH+a_); pal[i]=__ldg(PL+a_); } \
    } else { \
        _Pragma("unroll") for (int i=0;i<8;i++){ \
            int k0=c_*32+(ah_*8+i)*2; \
            int ic0_=k0/9, t0_=k0-ic0_*9; int k1=k0+1; int ic1_=k1/9, t1_=k1-ic1_*9; \
            ushort h0=0,h1=0,l0=0,l1=0; \
            { int gy=y-1+t0_/3, gx=apx-1+t0_%3; \
              if ((unsigned)gy<128u&&(unsigned)gx<128u){ \
                size_t a_=((size_t)(n*cin+ic0_))*HWSZ+gy*WW+gx; h0=__ldg(XH+a_); l0=__ldg(XL+a_);} } \
            { int gy=y-1+t1_/3, gx=apx-1+t1_%3; \
              if ((unsigned)gy<128u&&(unsigned)gx<128u){ \
                size_t a_=((size_t)(n*cin+ic1_))*HWSZ+gy*WW+gx; h1=__ldg(XH+a_); l1=__ldg(XL+a_);} } \
            pah[i]=(uint32_t)h0|((uint32_t)h1<<16); \
            pal[i]=(uint32_t)l0|((uint32_t)l1<<16); } \
    } \
    { const uint32_t wb=((uint32_t)c_*coutPad+ocb)*16; \
      _Pragma("unroll") for (int j=0;j<NF8;j++){ \
          pbh[j]=__ldg(WH+wb+tid+256*j); pbl[j]=__ldg(WL+wb+tid+256*j); } } }

#define G_STORE(B) { uint32_t* bb = sm + (B)*PB; \
    _Pragma("unroll") for (int i=0;i<8;i++){ \
        int word = apx*18 + ah_*8 + i; \
        bb[word] = pah[i]; bb[AW + word] = pal[i]; } \
    _Pragma("unroll") for (int j=0;j<NF8;j++){ \
        int idx = tid + 256*j; int oc = idx>>4, kp = idx&15; \
        int word = oc*18 + kp; \
        bb[2*AW + word] = pbh[j]; bb[2*AW + BW + word] = pbl[j]; } }

    float acc[2][NF8][4];
#pragma unroll
    for (int mt=0;mt<2;mt++)
#pragma unroll
        for (int j=0;j<NF8;j++)
#pragma unroll
            for (int q=0;q<4;q++) acc[mt][j][q]=0.f;

    G_LOAD(0); G_STORE(0); __syncthreads();

    for (int c=0;c<nch;c++){
        const int b=c&1;
        if (c+1<nch) G_LOAD(c+1);
        const uint32_t* Ah = sm + b*PB;
        const uint32_t* Al = Ah + AW;
        const uint32_t* Bh = Ah + 2*AW;
        const uint32_t* Bl = Bh + BW;
#pragma unroll
        for (int ks=0;ks<2;ks++){
            uint32_t ha[2][4], la[2][4];
#pragma unroll
            for (int mt=0;mt<2;mt++){
                int r = mIdx + mt*16 + g;
                int w0 = r*18 + ks*8 + tig;
                ha[mt][0]=Ah[w0];        ha[mt][1]=Ah[w0+8*18];
                ha[mt][2]=Ah[w0+4];      ha[mt][3]=Ah[w0+8*18+4];
                la[mt][0]=Al[w0];        la[mt][1]=Al[w0+8*18];
                la[mt][2]=Al[w0+4];      la[mt][3]=Al[w0+8*18+4];
            }
#pragma unroll
            for (int j=0;j<NF8;j++){
                int cc = nIdx + j*8 + g;
                int w0 = cc*18 + ks*8 + tig;
                uint32_t bh0=Bh[w0], bh1=Bh[w0+4];
                uint32_t bl0=Bl[w0], bl1=Bl[w0+4];
#pragma unroll
                for (int mt=0;mt<2;mt++){
                    MMA4(acc[mt][j], ha[mt][0],ha[mt][1],ha[mt][2],ha[mt][3], bh0,bh1);
                    MMA4(acc[mt][j], la[mt][0],la[mt][1],la[mt][2],la[mt][3], bh0,bh1);
                    MMA4(acc[mt][j], ha[mt][0],ha[mt][1],ha[mt][2],ha[mt][3], bl0,bl1);
                }
            }
        }
        if (c+1<nch){ G_STORE((c+1)&1); __syncthreads(); }
    }

#pragma unroll
    for (int mt=0;mt<2;mt++){
        int px0 = mIdx + mt*16 + g;
#pragma unroll
        for (int j=0;j<NF8;j++){
            int oc0 = ocb + nIdx + j*8 + 2*tig;
#pragma unroll
            for (int q=0;q<4;q++){
                int oc = oc0 + (q&1);
                int px = px0 + ((q>>1)*8);
                if (oc < cout){
                    float v = acc[mt][j][q] + bias[oc];
                    if (flags&1) v=(v>=0.f)?v:0.1f*v;
                    float* op = out + ((size_t)(n*cout+oc)*HH + y)*WW + px;
                    if (flags&2) *op += v; else *op = v;
                }
            }
        }
    }
#undef G_LOAD
#undef G_STORE
}

// ------------------------------ launch ---------------------------------------
extern "C" void kernel_launch(void* const* d_in, const int* in_sizes, int n_in,
                              void* d_out, int out_size)
{
    const float* ref   = (const float*)d_in[0];
    const float* inp   = (const float*)d_in[1];
    const float* w_oc1 = (const float*)d_in[2];  const float* b_oc1 = (const float*)d_in[3];
    const float* w_oc3 = (const float*)d_in[4];  const float* b_oc3 = (const float*)d_in[5];
    const float* w_e1  = (const float*)d_in[6];  const float* b_e1  = (const float*)d_in[7];
    const float* w_e2  = (const float*)d_in[8];  const float* b_e2  = (const float*)d_in[9];
    const float* w_d1  = (const float*)d_in[10]; const float* b_d1  = (const float*)d_in[11];
    const float* w_d2  = (const float*)d_in[12]; const float* b_d2  = (const float*)d_in[13];
    const float* w_off = (const float*)d_in[14]; const float* b_off = (const float*)d_in[15];
    const float* w_dcn = (const float*)d_in[16]; const float* b_dcn = (const float*)d_in[17];
    const float* w_c1  = (const float*)d_in[18]; const float* b_c1  = (const float*)d_in[19];
    const float* w_c2  = (const float*)d_in[20]; const float* b_c2  = (const float*)d_in[21];

    float* out  = (float*)d_out;
    float* oL1  = out;
    float* oEN  = out + (size_t)BN*NF*HWSZ;
    float* oQ   = oEN + (size_t)BN*NF*32*32;
    float* oDEC = oQ  + (size_t)BN*NF*32*32;

    float *t1, *t2, *e1b, *d1b, *offb;
    ushort *xh, *xl;
    uint32_t *sh, *sl, *wh, *wl;
    cudaGetSymbolAddress((void**)&t1,   g_t1);
    cudaGetSymbolAddress((void**)&t2,   g_t2);
    cudaGetSymbolAddress((void**)&e1b,  g_e1);
    cudaGetSymbolAddress((void**)&d1b,  g_d1);
    cudaGetSymbolAddress((void**)&offb, g_off);
    cudaGetSymbolAddress((void**)&xh,   g_xh);
    cudaGetSymbolAddress((void**)&xl,   g_xl);
    cudaGetSymbolAddress((void**)&sh,   g_sh);
    cudaGetSymbolAddress((void**)&sl,   g_sl);
    cudaGetSymbolAddress((void**)&wh,   g_wh);
    cudaGetSymbolAddress((void**)&wl,   g_wl);

    // weight pre-split (offsets: off 0 / dcn 96768 / c1 138240 / c2 221184)
    w_prep<<<27, 256>>>(w_off, 864,  216, 224, wh,          wl);
    w_prep<<<27, 256>>>(w_dcn, 864,  96,  96,  wh + 96768,  wl + 96768);
    w_prep<<<54, 256>>>(w_c1,  1728, 96,  96,  wh + 138240, wl + 138240);
    w_prep<<<27, 256>>>(w_c2,  864,  96,  96,  wh + 221184, wl + 221184);

    const int smem7 = (2*(2*128*18 + 2*112*18))*4;
    const int smem6 = (2*(2*128*18 + 2*96*18))*4;
    cudaFuncSetAttribute(gemm_tc<7,0>, cudaFuncAttributeMaxDynamicSharedMemorySize, smem7);
    cudaFuncSetAttribute(gemm_tc<6,0>, cudaFuncAttributeMaxDynamicSharedMemorySize, smem6);
    cudaFuncSetAttribute(gemm_tc<6,1>, cudaFuncAttributeMaxDynamicSharedMemorySize, smem6);

    conv3x3_s1v2<<<dim3(16, 12, BN), 256>>>(ref, NF, inp, NF, w_oc1, b_oc1, t1, NF, 1);
    conv3x3_s1v2<<<dim3(16, 12, BN), 256>>>(t1, NF, nullptr, 0, w_oc3, b_oc3, t2, NF, 1);
    conv3x3_s2v2<<<dim3(16, 12, BN), 256>>>(t2, 128, w_e1, b_e1, e1b, nullptr, 1);
    conv3x3_s2v2<<<dim3(4,  12, BN), 256>>>(e1b, 64, w_e2, b_e2, oEN, oQ, 0);
    deconv3x3_x2<<<dim3(4,  12, BN), 256>>>(oQ,  32, w_d1, b_d1, d1b, 1);
    deconv3x3_x2<<<dim3(16, 12, BN), 256>>>(d1b, 64, w_d2, b_d2, oDEC, 0);

    // offset head: split dec, GEMM (216ch in 2 blocks of 112)
    split_tensor<<<(BN*96*HWSZ/2+255)/256, 256>>>(oDEC, xh, xl, 96, 0, 96);
    gemm_tc<7,0><<<dim3(128, 2, BN), 256, smem7>>>(xh, xl, 96, wh, wl, 224, b_off, offb, 216, 0);
    // DCN: sample (emits bf16 planes) + GEMM over 864 ch
    dcn_sample<<<(BN*GD*K2T*HWSZ)/256, 256>>>(ref, offb, (ushort*)sh, (ushort*)sl);
    gemm_tc<6,1><<<dim3(128, 1, BN), 256, smem6>>>((const ushort*)sh, (const ushort*)sl, 864,
                                                   wh + 96768, wl + 96768, 96, b_dcn, oL1, 96, 0);
    // fusion tail: c1 on concat(L1, ref), c2 with += into L1
    split_tensor<<<(BN*96*HWSZ/2+255)/256, 256>>>(oL1, xh, xl, 96, 0, 192);
    split_tensor<<<(BN*96*HWSZ/2+255)/256, 256>>>(ref, xh, xl, 96, 96, 192);
    gemm_tc<6,0><<<dim3(128, 1, BN), 256, smem6>>>(xh, xl, 192, wh + 138240, wl + 138240, 96, b_c1, t1, 96, 1);
    split_tensor<<<(BN*96*HWSZ/2+255)/256, 256>>>(t1, xh, xl, 96, 0, 96);
    gemm_tc<6,0><<<dim3(128, 1, BN), 256, smem6>>>(xh, xl, 96, wh + 221184, wl + 221184, 96, b_c2, oL1, 96, 3);
}

// round 11
// speedup vs baseline: 1.4820x; 1.4820x over previous
#include <cuda_runtime.h>
#include <cuda_bf16.h>
#include <math.h>
#include <stdint.h>

#define NF 96
#define GD 12
#define K2T 9
#define BN 4
#define HH 128
#define WW 128
#define HWSZ (HH*WW)

__device__ float g_t1[BN*NF*HWSZ];
__device__ float g_t2[BN*NF*HWSZ];
__device__ float g_e1[BN*NF*64*64];
__device__ float g_d1[BN*NF*64*64];
__device__ float g_off[BN*2*GD*K2T*HWSZ];
__device__ float g_S[BN*NF*K2T*HWSZ];

// ---------------- fp32 pipelined 3x3 s1 conv (oc1, oc3) ----------------------
__global__ __launch_bounds__(256) void conv3x3_s1v2(
    const float* __restrict__ inA, int cinA,
    const float* __restrict__ inB, int cinB,
    const float* __restrict__ w, const float* __restrict__ bias,
    float* __restrict__ out, int cout, int flags)
{
    const int tid = threadIdx.x;
    const int tx = tid & 15, ty = tid >> 4;
    const int x0 = (blockIdx.x & 1) * 64, y0 = (blockIdx.x >> 1) * 16;
    const int ocb = blockIdx.y * 8, n = blockIdx.z;
    const int cin = cinA + cinB, nch = cin >> 2;
    __shared__ float sIn[2][4][18][68];
    __shared__ float sW[2][8*4*9];
    float rI[19]; float rw0, rw1;

#define S1_LOAD(IC0) { const int ic0_=(IC0); \
    _Pragma("unroll") for (int k=0;k<19;k++){ int idx=tid+256*k; \
      if (k<18||tid<144){ int ic=idx/1188; int rem=idx-ic*1188; int rr=rem/66; int cc=rem-rr*66; \
        int gy=y0-1+rr, gx=x0-1+cc; bool inb=((unsigned)gy<(unsigned)HH)&&((unsigned)gx<(unsigned)WW); \
        int icg=ic0_+ic; const float* p=(icg<cinA)?(inA+((size_t)(n*cinA+icg)*HH+gy)*WW+gx):(inB+((size_t)(n*cinB+(icg-cinA))*HH+gy)*WW+gx); \
        rI[k]=inb?__ldg(p):0.f; } } \
    { int o=tid/36, ic=(tid/9)%4, t=tid%9; rw0=w[((size_t)(ocb+o)*cin+ic0_+ic)*9+t]; \
      if (tid<32){ int idx=tid+256; int o2=idx/36, ic2=(idx/9)%4, t2=idx%9; rw1=w[((size_t)(ocb+o2)*cin+ic0_+ic2)*9+t2]; } } }
#define S1_STORE(B) { float* sb=&sIn[B][0][0][0]; \
    _Pragma("unroll") for (int k=0;k<19;k++){ int idx=tid+256*k; \
      if (k<18||tid<144){ int ic=idx/1188; int rem=idx-ic*1188; int rr=rem/66; int cc=rem-rr*66; \
        sb[(ic*18+rr)*68+cc]=rI[k]; } } \
    sW[B][tid]=rw0; if (tid<32) sW[B][tid+256]=rw1; }

    float acc[8][4];
#pragma unroll
    for (int o=0;o<8;o++)
#pragma unroll
      for (int j=0;j<4;j++) acc[o][j]=0.f;
    S1_LOAD(0); S1_STORE(0); __syncthreads();
    for (int c=0;c<nch;c++){
        const int b=c&1;
        if (c+1<nch) S1_LOAD((c+1)*4);
#pragma unroll
        for (int ic=0;ic<4;ic++){
#pragma unroll
            for (int dy=0;dy<3;dy++){
                const float* rp=&sIn[b][ic][ty+dy][4*tx];
                float4 va=*(const float4*)rp; float2 vb=*(const float2*)(rp+4);
                float v[6]={va.x,va.y,va.z,va.w,vb.x,vb.y};
                const float* wrow=&sW[b][ic*9+dy*3];
#pragma unroll
                for (int dx=0;dx<3;dx++){
                    float wv[8];
#pragma unroll
                    for (int o=0;o<8;o++) wv[o]=wrow[o*36+dx];
#pragma unroll
                    for (int j=0;j<4;j++){ float xv=v[j+dx];
#pragma unroll
                        for (int o=0;o<8;o++) acc[o][j]=fmaf(wv[o],xv,acc[o][j]); }
                }
            }
        }
        if (c+1<nch){ S1_STORE((c+1)&1); __syncthreads(); }
    }
    const int y=y0+ty, xb=x0+4*tx;
#pragma unroll
    for (int o=0;o<8;o++){
        float bv=bias[ocb+o];
        float v0=acc[o][0]+bv,v1=acc[o][1]+bv,v2=acc[o][2]+bv,v3=acc[o][3]+bv;
        if (flags&1){ v0=(v0>=0.f)?v0:0.1f*v0; v1=(v1>=0.f)?v1:0.1f*v1; v2=(v2>=0.f)?v2:0.1f*v2; v3=(v3>=0.f)?v3:0.1f*v3; }
        float* op=out+((size_t)(n*cout+ocb+o)*HH+y)*WW+xb;
        if (flags&2){ float4 p=*(float4*)op; p.x+=v0;p.y+=v1;p.z+=v2;p.w+=v3; *(float4*)op=p; }
        else *(float4*)op=make_float4(v0,v1,v2,v3);
    }
#undef S1_LOAD
#undef S1_STORE
}

// ---------------- fp32 pipelined 3x3 s2 conv (e1, e2) ------------------------
__global__ __launch_bounds__(256) void conv3x3_s2v2(
    const float* __restrict__ in, int Hin,
    const float* __restrict__ w, const float* __restrict__ bias,
    float* __restrict__ out, float* __restrict__ out_q, int flags)
{
    const int tid=threadIdx.x, tx=tid&15, ty=tid>>4;
    const int Hout=Hin>>1, tilesX=Hout>>4;
    const int x0=(blockIdx.x%tilesX)*16, y0=(blockIdx.x/tilesX)*16;
    const int ocb=blockIdx.y*8, n=blockIdx.z;
    __shared__ float sIn[2][2][33][34];
    __shared__ float sW[2][8*2*9];
    float rI[9]; float rw0;
#define S2_LOAD(IC0) { const int ic0_=(IC0); \
    _Pragma("unroll") for (int k=0;k<9;k++){ int idx=tid+256*k; \
      if (k<8||tid<130){ int ic=idx/1089; int rem=idx-ic*1089; int rr=rem/33; int cc=rem-rr*33; \
        int gy=2*y0+rr, gx=2*x0+cc; bool inb=(gy<Hin)&&(gx<Hin); \
        rI[k]=inb?__ldg(in+((size_t)(n*NF+ic0_+ic)*Hin+gy)*Hin+gx):0.f; } } \
    if (tid<144){ int o=tid/18, ic=(tid/9)%2, t=tid%9; rw0=w[((size_t)(ocb+o)*NF+ic0_+ic)*9+t]; } }
#define S2_STORE(B) { float* sb=&sIn[B][0][0][0]; \
    _Pragma("unroll") for (int k=0;k<9;k++){ int idx=tid+256*k; \
      if (k<8||tid<130){ int ic=idx/1089; int rem=idx-ic*1089; int rr=rem/33; int cc=rem-rr*33; \
        sb[(ic*33+rr)*34+cc]=rI[k]; } } \
    if (tid<144) sW[B][tid]=rw0; }
    float acc[8];
#pragma unroll
    for (int o=0;o<8;o++) acc[o]=0.f;
    S2_LOAD(0); S2_STORE(0); __syncthreads();
    const int nch=NF/2;
    for (int c=0;c<nch;c++){
        const int b=c&1;
        if (c+1<nch) S2_LOAD((c+1)*2);
#pragma unroll
        for (int ic=0;ic<2;ic++)
#pragma unroll
            for (int dy=0;dy<3;dy++)
#pragma unroll
                for (int dx=0;dx<3;dx++){
                    float xv=sIn[b][ic][2*ty+dy][2*tx+dx];
                    const float* wp=&sW[b][ic*9+dy*3+dx];
#pragma unroll
                    for (int o=0;o<8;o++) acc[o]=fmaf(wp[o*18],xv,acc[o]);
                }
        if (c+1<nch){ S2_STORE((c+1)&1); __syncthreads(); }
    }
#pragma unroll
    for (int o=0;o<8;o++){
        float v=acc[o]+bias[ocb+o];
        if (flags&1) v=(v>=0.f)?v:0.1f*v;
        size_t oi=((size_t)(n*NF+ocb+o)*Hout+(y0+ty))*Hout+(x0+tx);
        out[oi]=v;
        if (out_q) out_q[oi]=rintf(v);
    }
#undef S2_LOAD
#undef S2_STORE
}

// ---------------- fp32 transpose conv (d1, d2) --------------------------------
__global__ __launch_bounds__(256) void deconv3x3_x2(
    const float* __restrict__ in, int Hin,
    const float* __restrict__ w, const float* __restrict__ bias,
    float* __restrict__ out, int flags)
{
    const int tid=threadIdx.x, tx=tid&15, ty=tid>>4;
    const int Hout=Hin*2, tilesX=Hout>>5;
    const int tX=blockIdx.x%tilesX, tY=blockIdx.x/tilesX;
    const int xin0=tX*16, yin0=tY*16, x0o=tX*32, y0o=tY*32;
    const int ocb=blockIdx.y*8, n=blockIdx.z;
    __shared__ float sIn[4][17][18];
    __shared__ float sW[8][4][9];
    float aEE[8],aEO[8],aOE[8],aOO[8];
#pragma unroll
    for (int o=0;o<8;o++){aEE[o]=0.f;aEO[o]=0.f;aOE[o]=0.f;aOO[o]=0.f;}
    for (int ic0=0;ic0<NF;ic0+=4){
        __syncthreads();
        for (int idx=tid;idx<4*17*17;idx+=256){
            int ic=idx/(17*17), r=(idx/17)%17, c=idx%17;
            int gy=yin0-1+r, gx=xin0-1+c;
            float v=0.f;
            if ((unsigned)gy<(unsigned)Hin&&(unsigned)gx<(unsigned)Hin)
                v=in[((size_t)(n*NF+ic0+ic)*Hin+gy)*Hin+gx];
            sIn[ic][r][c]=v;
        }
        for (int idx=tid;idx<8*4*9;idx+=256){
            int o=idx/36, ic=(idx/9)%4, t=idx%9;
            sW[o][ic][t]=w[((size_t)(ocb+o)*NF+ic0+ic)*9+t];
        }
        __syncthreads();
#pragma unroll
        for (int ic=0;ic<4;ic++){
            float v00=sIn[ic][ty][tx], v01=sIn[ic][ty][tx+1];
            float v10=sIn[ic][ty+1][tx], v11=sIn[ic][ty+1][tx+1];
#pragma unroll
            for (int o=0;o<8;o++){
                const float* wp=&sW[o][ic][0];
                aEE[o]=fmaf(wp[0],v00,aEE[o]); aEE[o]=fmaf(wp[2],v01,aEE[o]);
                aEE[o]=fmaf(wp[6],v10,aEE[o]); aEE[o]=fmaf(wp[8],v11,aEE[o]);
                aEO[o]=fmaf(wp[1],v01,aEO[o]); aEO[o]=fmaf(wp[7],v11,aEO[o]);
                aOE[o]=fmaf(wp[3],v10,aOE[o]); aOE[o]=fmaf(wp[5],v11,aOE[o]);
                aOO[o]=fmaf(wp[4],v11,aOO[o]);
            }
        }
    }
    const int ye=y0o+2*ty, xe=x0o+2*tx;
#pragma unroll
    for (int o=0;o<8;o++){
        float bv=bias[ocb+o];
        float vEE=aEE[o]+bv,vEO=aEO[o]+bv,vOE=aOE[o]+bv,vOO=aOO[o]+bv;
        if (flags&1){ vEE=(vEE>=0.f)?vEE:0.1f*vEE; vEO=(vEO>=0.f)?vEO:0.1f*vEO;
                      vOE=(vOE>=0.f)?vOE:0.1f*vOE; vOO=(vOO>=0.f)?vOO:0.1f*vOO; }
        size_t base=((size_t)(n*NF+ocb+o)*Hout+ye)*Hout+xe;
        out[base]=vEE; out[base+1]=vEO; out[base+Hout]=vOE; out[base+Hout+1]=vOO;
    }
}

// ---------------- DCN sampling ------------------------------------------------
__global__ __launch_bounds__(256) void dcn_sample(
    const float* __restrict__ ref, const float* __restrict__ off,
    float* __restrict__ S)
{
    int idx=blockIdx.x*256+threadIdx.x;
    if (idx>=BN*GD*K2T*HWSZ) return;
    int p=idx&(HWSZ-1); int t=idx>>14;
    int k=t%9; t/=9; int g=t%GD, n=t/GD;
    int y=p>>7, x=p&127;
    int offc=(g*9+k)*2;
    float dy=off[((size_t)(n*2*GD*K2T+offc))*HWSZ+p];
    float dx=off[((size_t)(n*2*GD*K2T+offc+1))*HWSZ+p];
    float py=(float)y+(float)(k/3-1)+dy;
    float px=(float)x+(float)(k%3-1)+dx;
    float fy=floorf(py), fx=floorf(px);
    float wy=py-fy, wx=px-fx;
    int iy=(int)fy, ix=(int)fx;
    float wgt[4]; int ofs[4];
#pragma unroll
    for (int r=0;r<2;r++)
#pragma unroll
        for (int c=0;c<2;c++){
            int yy=iy+r, xx=ix+c;
            bool val=((unsigned)yy<(unsigned)HH)&&((unsigned)xx<(unsigned)WW);
            float wv=(r?wy:1.f-wy)*(c?wx:1.f-wx);
            wgt[r*2+c]=val?wv:0.f; ofs[r*2+c]=val?(yy*WW+xx):0;
        }
    const float* base=ref+(size_t)(n*NF+g*8)*HWSZ;
    float* so=S+((size_t)(n*NF+g*8)*9+k)*HWSZ+p;
#pragma unroll
    for (int c=0;c<8;c++){
        const float* bp=base+(size_t)c*HWSZ;
        so[(size_t)c*9*HWSZ]=wgt[0]*bp[ofs[0]]+wgt[1]*bp[ofs[1]]+wgt[2]*bp[ofs[2]]+wgt[3]*bp[ofs[3]];
    }
}

// ================= mma.sync bf16 split-3 implicit GEMM (ldmatrix, 80B rows) ==
__device__ __forceinline__ void split2(float v0, float v1, uint32_t& hi, uint32_t& lo){
    __nv_bfloat16 h0=__float2bfloat16(v0), h1=__float2bfloat16(v1);
    __nv_bfloat16 l0=__float2bfloat16(v0-__bfloat162float(h0));
    __nv_bfloat16 l1=__float2bfloat16(v1-__bfloat162float(h1));
    hi=((uint32_t)__bfloat16_as_ushort(h1)<<16)|__bfloat16_as_ushort(h0);
    lo=((uint32_t)__bfloat16_as_ushort(l1)<<16)|__bfloat16_as_ushort(l0);
}
#define MMA4(d,a0,a1,a2,a3,b0,b1) \
    asm volatile("mma.sync.aligned.m16n8k16.row.col.f32.bf16.bf16.f32 " \
        "{%0,%1,%2,%3},{%4,%5,%6,%7},{%8,%9},{%0,%1,%2,%3};" \
        : "+f"(d[0]),"+f"(d[1]),"+f"(d[2]),"+f"(d[3]) \
        : "r"(a0),"r"(a1),"r"(a2),"r"(a3),"r"(b0),"r"(b1))
#define LDSM4(r0,r1,r2,r3,a) \
    asm volatile("ldmatrix.sync.aligned.m8n8.x4.shared.b16 {%0,%1,%2,%3},[%4];" \
        : "=r"(r0),"=r"(r1),"=r"(r2),"=r"(r3) : "r"(a))
#define LDSM2(r0,r1,a) \
    asm volatile("ldmatrix.sync.aligned.m8n8.x2.shared.b16 {%0,%1},[%2];" \
        : "=r"(r0),"=r"(r1) : "r"(a))

template<int NF8, int MODE>
__global__ __launch_bounds__(256) void gemm_tc(
    const float* __restrict__ inA, int cinA,
    const float* __restrict__ inB, int cinB,
    const float* __restrict__ w, const float* __restrict__ bias,
    float* __restrict__ out, int cout, int flags)
{
    extern __shared__ uint32_t sm[];
    const int Ncta = NF8*16;
    const int AW = 128*20, BW = Ncta*20, PB = 2*AW + 2*BW;
    const int tid=threadIdx.x, lane=tid&31, wid=tid>>5;
    const int g=lane>>2, tig=lane&3;
    const int y=blockIdx.x, n=blockIdx.z;
    const int ocb = blockIdx.y * Ncta;
    const int cin = cinA + cinB;
    const int K = MODE ? cin : cin*9;
    const int nch = K/32;
    const int mIdx = (wid&3)*32, nIdx = (wid>>2)*NF8*8;
    const int apx = tid & 127, ah_ = tid >> 7;

    // ldmatrix shared-space byte addresses; rows are 80B (16B-aligned) apart
    const uint32_t smb = (uint32_t)__cvta_generic_to_shared(sm);
    const uint32_t PB4 = PB*4, AW4 = AW*4, BW4 = BW*4;
    const uint32_t rowA = (uint32_t)((mIdx + (lane&15))*80) + ((lane&16)?16u:0u);
    const uint32_t rowB = (uint32_t)((nIdx + (lane&7))*80) + ((lane&8)?16u:0u);

    uint32_t pah[8], pal[8], pbh[NF8], pbl[NF8];

#define FETCH_A(kk, dst) { float vv=0.f; int k_=(kk); \
    if (MODE){ vv = __ldg(inA + ((size_t)(n*cin + k_))*HWSZ + y*WW + apx); } \
    else { int ic_=k_/9, tp_=k_-ic_*9; int gy=y-1+tp_/3, gx=apx-1+tp_%3; \
        if ((unsigned)gy<(unsigned)HH && (unsigned)gx<(unsigned)WW){ \
            const float* p_=(ic_<cinA)? inA+((size_t)(n*cinA+ic_)*HH+gy)*WW+gx \
                                      : inB+((size_t)(n*cinB+(ic_-cinA))*HH+gy)*WW+gx; \
            vv=__ldg(p_); } } \
    dst=vv; }

#define G_LOAD(C) { const int c_=(C); \
    _Pragma("unroll") for (int i=0;i<8;i++){ \
        int k0 = c_*32 + (ah_*8+i)*2; \
        float v0, v1; FETCH_A(k0, v0); FETCH_A(k0+1, v1); \
        split2(v0, v1, pah[i], pal[i]); } \
    _Pragma("unroll") for (int j=0;j<NF8;j++){ \
        int idx = tid + 256*j; int oc = idx>>4, kp = idx&15; \
        int k0 = c_*32 + kp*2; int ocg = ocb + oc; \
        float v0=0.f, v1=0.f; \
        if (ocg < cout){ \
            if (MODE){ v0=__ldg(w+(size_t)ocg*cin+k0); v1=__ldg(w+(size_t)ocg*cin+k0+1); } \
            else { int ic0_=k0/9, t0_=k0-ic0_*9; v0=__ldg(w+((size_t)ocg*cin+ic0_)*9+t0_); \
                   int k1=k0+1; int ic1_=k1/9, t1_=k1-ic1_*9; v1=__ldg(w+((size_t)ocg*cin+ic1_)*9+t1_); } } \
        split2(v0, v1, pbh[j], pbl[j]); } }

#define G_STORE(B) { uint32_t* bb = sm + (B)*PB; \
    _Pragma("unroll") for (int i=0;i<8;i++){ \
        int word = apx*20 + ah_*8 + i; \
        bb[word] = pah[i]; bb[AW + word] = pal[i]; } \
    _Pragma("unroll") for (int j=0;j<NF8;j++){ \
        int idx = tid + 256*j; int oc = idx>>4, kp = idx&15; \
        int word = oc*20 + kp; \
        bb[2*AW + word] = pbh[j]; bb[2*AW + BW + word] = pbl[j]; } }

    float acc[2][NF8][4];
#pragma unroll
    for (int mt=0;mt<2;mt++)
#pragma unroll
        for (int j=0;j<NF8;j++)
#pragma unroll
            for (int q=0;q<4;q++) acc[mt][j][q]=0.f;

    G_LOAD(0); G_STORE(0); __syncthreads();

    for (int c=0;c<nch;c++){
        const int b=c&1;
        if (c+1<nch) G_LOAD(c+1);
        const uint32_t base = smb + b*PB4;
#pragma unroll
        for (int ks=0;ks<2;ks++){
            const uint32_t aoff = base + (uint32_t)(ks*32) + rowA;
            uint32_t ha[2][4], la[2][4];
#pragma unroll
            for (int mt=0;mt<2;mt++){
                LDSM4(ha[mt][0],ha[mt][1],ha[mt][2],ha[mt][3], aoff + mt*1280u);
                LDSM4(la[mt][0],la[mt][1],la[mt][2],la[mt][3], aoff + AW4 + mt*1280u);
            }
            const uint32_t boff0 = base + 2u*AW4 + (uint32_t)(ks*32) + rowB;
#pragma unroll
            for (int j=0;j<NF8;j++){
                uint32_t bh0,bh1,bl0,bl1;
                const uint32_t boff = boff0 + j*640u;
                LDSM2(bh0,bh1, boff);
                LDSM2(bl0,bl1, boff + BW4);
#pragma unroll
                for (int mt=0;mt<2;mt++){
                    MMA4(acc[mt][j], ha[mt][0],ha[mt][1],ha[mt][2],ha[mt][3], bh0,bh1);
                    MMA4(acc[mt][j], la[mt][0],la[mt][1],la[mt][2],la[mt][3], bh0,bh1);
                    MMA4(acc[mt][j], ha[mt][0],ha[mt][1],ha[mt][2],ha[mt][3], bl0,bl1);
                }
            }
        }
        if (c+1<nch){ G_STORE((c+1)&1); __syncthreads(); }
    }

    // epilogue: d0:(px,oc0) d1:(px,oc0+1) d2:(px+8,oc0) d3:(px+8,oc0+1)
#pragma unroll
    for (int mt=0;mt<2;mt++){
        int px0 = mIdx + mt*16 + g;
#pragma unroll
        for (int j=0;j<NF8;j++){
            int oc0 = ocb + nIdx + j*8 + 2*tig;
#pragma unroll
            for (int q=0;q<4;q++){
                int oc = oc0 + (q&1);
                int px = px0 + ((q>>1)*8);
                if (oc < cout){
                    float v = acc[mt][j][q] + bias[oc];
                    if (flags&1) v=(v>=0.f)?v:0.1f*v;
                    float* op = out + ((size_t)(n*cout+oc)*HH + y)*WW + px;
                    if (flags&2) *op += v; else *op = v;
                }
            }
        }
    }
#undef FETCH_A
#undef G_LOAD
#undef G_STORE
}

// ------------------------------ launch ---------------------------------------
extern "C" void kernel_launch(void* const* d_in, const int* in_sizes, int n_in,
                              void* d_out, int out_size)
{
    const float* ref   = (const float*)d_in[0];
    const float* inp   = (const float*)d_in[1];
    const float* w_oc1 = (const float*)d_in[2];  const float* b_oc1 = (const float*)d_in[3];
    const float* w_oc3 = (const float*)d_in[4];  const float* b_oc3 = (const float*)d_in[5];
    const float* w_e1  = (const float*)d_in[6];  const float* b_e1  = (const float*)d_in[7];
    const float* w_e2  = (const float*)d_in[8];  const float* b_e2  = (const float*)d_in[9];
    const float* w_d1  = (const float*)d_in[10]; const float* b_d1  = (const float*)d_in[11];
    const float* w_d2  = (const float*)d_in[12]; const float* b_d2  = (const float*)d_in[13];
    const float* w_off = (const float*)d_in[14]; const float* b_off = (const float*)d_in[15];
    const float* w_dcn = (const float*)d_in[16]; const float* b_dcn = (const float*)d_in[17];
    const float* w_c1  = (const float*)d_in[18]; const float* b_c1  = (const float*)d_in[19];
    const float* w_c2  = (const float*)d_in[20]; const float* b_c2  = (const float*)d_in[21];

    float* out  = (float*)d_out;
    float* oL1  = out;
    float* oEN  = out + (size_t)BN*NF*HWSZ;
    float* oQ   = oEN + (size_t)BN*NF*32*32;
    float* oDEC = oQ  + (size_t)BN*NF*32*32;

    float *t1, *t2, *e1b, *d1b, *offb, *Sb;
    cudaGetSymbolAddress((void**)&t1,   g_t1);
    cudaGetSymbolAddress((void**)&t2,   g_t2);
    cudaGetSymbolAddress((void**)&e1b,  g_e1);
    cudaGetSymbolAddress((void**)&d1b,  g_d1);
    cudaGetSymbolAddress((void**)&offb, g_off);
    cudaGetSymbolAddress((void**)&Sb,   g_S);

    const int smem7 = (2*(2*128*20 + 2*112*20))*4;   // 76800
    const int smem6 = (2*(2*128*20 + 2*96*20))*4;    // 71680
    cudaFuncSetAttribute(gemm_tc<7,0>, cudaFuncAttributeMaxDynamicSharedMemorySize, smem7);
    cudaFuncSetAttribute(gemm_tc<6,0>, cudaFuncAttributeMaxDynamicSharedMemorySize, smem6);
    cudaFuncSetAttribute(gemm_tc<6,1>, cudaFuncAttributeMaxDynamicSharedMemorySize, smem6);

    conv3x3_s1v2<<<dim3(16, 12, BN), 256>>>(ref, NF, inp, NF, w_oc1, b_oc1, t1, NF, 1);
    conv3x3_s1v2<<<dim3(16, 12, BN), 256>>>(t1, NF, nullptr, 0, w_oc3, b_oc3, t2, NF, 1);
    conv3x3_s2v2<<<dim3(16, 12, BN), 256>>>(t2, 128, w_e1, b_e1, e1b, nullptr, 1);
    conv3x3_s2v2<<<dim3(4,  12, BN), 256>>>(e1b, 64, w_e2, b_e2, oEN, oQ, 0);
    deconv3x3_x2<<<dim3(4,  12, BN), 256>>>(oQ,  32, w_d1, b_d1, d1b, 1);
    deconv3x3_x2<<<dim3(16, 12, BN), 256>>>(d1b, 64, w_d2, b_d2, oDEC, 0);
    // offset head (216 ch): 2 oc-blocks of 112
    gemm_tc<7,0><<<dim3(128, 2, BN), 256, smem7>>>(oDEC, NF, nullptr, 0, w_off, b_off, offb, 216, 0);
    dcn_sample<<<(BN*GD*K2T*HWSZ)/256, 256>>>(ref, offb, Sb);
    // DCN 1x1 GEMM over 864 channels
    gemm_tc<6,1><<<dim3(128, 1, BN), 256, smem6>>>(Sb, NF*K2T, nullptr, 0, w_dcn, b_dcn, oL1, NF, 0);
    // fusion tail
    gemm_tc<6,0><<<dim3(128, 1, BN), 256, smem6>>>(oL1, NF, ref, NF, w_c1, b_c1, t1, NF, 1);
    gemm_tc<6,0><<<dim3(128, 1, BN), 256, smem6>>>(t1, NF, nullptr, 0, w_c2, b_c2, oL1, NF, 3);
}